// round 1
// baseline (speedup 1.0000x reference)
#include <cuda_runtime.h>
#include <math.h>

#define BB 2
#define HH 80
#define WW 80
#define NPIX (HH * WW)

// Scratch: per-center quadratic-form coefficients {a, 2b, c, penalty}
// penalty = 0 for active centers (seg > 0.7), 3e30 for inactive.
__device__ float4 g_coef[BB * NPIX];
__device__ int g_R;

// Kernel 1: per-center coefficients.
__global__ void coef_kernel(const float* __restrict__ var,
                            const float* __restrict__ seg) {
    int idx = blockIdx.x * blockDim.x + threadIdx.x;
    if (idx >= BB * NPIX) return;
    int b = idx / NPIX;
    int pix = idx - b * NPIX;
    const float* vb = var + b * 3 * NPIX;
    float v0 = vb[pix];
    float v1 = vb[NPIX + pix];
    float v2 = vb[2 * NPIX + pix];
    float vh = fmaxf(v0, 0.0f) + 1.0f;
    float vw = fmaxf(v1, 0.0f) + 1.0f;
    float theta = 3.14f / (1.0f + expf(-v2));   // 3.14 * sigmoid(v2)
    float s, co;
    sincosf(theta, &s, &co);
    float vh2 = vh * vh;
    float vw2 = vw * vw;
    float a  = co * co / (2.0f * vh2) + s * s / (2.0f * vw2);
    float bq = -2.0f * s * co / (4.0f * vh2) + 2.0f * s * co / (4.0f * vw2);
    float c  = s * s / (2.0f * vh2) + co * co / (2.0f * vw2);
    float pen = (seg[b * NPIX + pix] > 0.7f) ? 0.0f : 3.0e30f;
    g_coef[idx] = make_float4(a, 2.0f * bq, c, pen);
}

// Kernel 2: single-block max-reduce over variance channels 0,1 -> window radius R.
// E >= r^2 / (2*Vmax^2); output needs E <= -ln(0.7) ~ 0.356676,
// so centers with r > sqrt(2*0.356676)*Vmax = 0.84460*Vmax are irrelevant.
__global__ void radius_kernel(const float* __restrict__ var) {
    __shared__ float red[256];
    int tid = threadIdx.x;
    float m = 0.0f;
    // channels 0 and 1 are contiguous within each batch: [b*3*NPIX, b*3*NPIX + 2*NPIX)
    for (int i = tid; i < BB * 2 * NPIX; i += 256) {
        int b = i / (2 * NPIX);
        int rest = i - b * 2 * NPIX;
        m = fmaxf(m, var[b * 3 * NPIX + rest]);
    }
    red[tid] = m;
    __syncthreads();
    for (int s = 128; s > 0; s >>= 1) {
        if (tid < s) red[tid] = fmaxf(red[tid], red[tid + s]);
        __syncthreads();
    }
    if (tid == 0) {
        float vmax = fmaxf(red[0], 0.0f) + 1.0f;
        int R = (int)(0.84461f * vmax) + 1;  // +1 safety margin
        if (R > HH - 1) R = HH - 1;
        g_R = R;
    }
}

// Kernel 3: windowed min of quadratic form, then exp + threshold.
__global__ void __launch_bounds__(64) pool_kernel(float* __restrict__ out) {
    int j = blockIdx.x * 8 + threadIdx.x;   // output col (q)
    int i = blockIdx.y * 8 + threadIdx.y;   // output row (p)
    int b = blockIdx.z;
    int R = g_R;
    int r0 = max(i - R, 0), r1 = min(i + R, HH - 1);
    int c0 = max(j - R, 0), c1 = min(j + R, WW - 1);
    const float4* __restrict__ cf = g_coef + b * NPIX;

    float minE = 3.0e30f;
    for (int r = r0; r <= r1; r++) {
        float dx = (float)(i - r);
        float dx2 = dx * dx;
        const float4* __restrict__ row = cf + r * WW;
#pragma unroll 4
        for (int cc = c0; cc <= c1; cc++) {
            float4 k = __ldg(&row[cc]);
            float dy = (float)(j - cc);
            float E = fmaf(k.x, dx2, k.w);        // a*dx^2 + penalty
            E = fmaf(k.y, dx * dy, E);            // + 2b*dx*dy
            E = fmaf(k.z, dy * dy, E);            // + c*dy^2
            minE = fminf(minE, E);
        }
    }
    float pooled = expf(1e-7f - minE);            // exp(-minE + eps)
    out[(b * HH + i) * WW + j] = (pooled >= 0.7f) ? pooled : 0.0f;
}

extern "C" void kernel_launch(void* const* d_in, const int* in_sizes, int n_in,
                              void* d_out, int out_size) {
    const float* var = (const float*)d_in[0];   // [2,3,80,80]
    const float* seg = (const float*)d_in[1];   // [2,1,80,80]
    float* out = (float*)d_out;                 // [2,1,80,80]

    coef_kernel<<<(BB * NPIX + 255) / 256, 256>>>(var, seg);
    radius_kernel<<<1, 256>>>(var);
    pool_kernel<<<dim3(WW / 8, HH / 8, BB), dim3(8, 8)>>>(out);
}

// round 3
// speedup vs baseline: 1.5403x; 1.5403x over previous
#include <cuda_runtime.h>
#include <math.h>

#define BB 2
#define HH 80
#define WW 80
#define NPIX (HH * WW)
#define NBLK 100
#define NTHR 128

// Scratch: per-center quadratic-form coefficients {a, 2b, c, penalty}
// penalty = 0 for active centers (seg > 0.7), 3e30 for inactive.
__device__ float4 g_coef[BB * NPIX];
__device__ int g_varmax = 0;            // float bits of max(vh,vw) >= 1.0 (nonneg -> int-orderable)
__device__ unsigned g_bar = 0;          // phase-1 arrival counter
__device__ unsigned g_done = 0;         // exit counter (for self-reset)

__global__ void __launch_bounds__(NTHR) fused_kernel(const float* __restrict__ var,
                                                     const float* __restrict__ seg,
                                                     float* __restrict__ out) {
    const int tid = threadIdx.x;
    const int idx = blockIdx.x * NTHR + tid;   // 0..12799, one center / one pixel
    const int b = idx / NPIX;
    const int pix = idx - b * NPIX;

    // ---------------- Phase 1: per-center coefficients + vmax reduce ----------------
    {
        const float* vb = var + b * 3 * NPIX;
        float v0 = vb[pix];
        float v1 = vb[NPIX + pix];
        float v2 = vb[2 * NPIX + pix];
        float vh = fmaxf(v0, 0.0f) + 1.0f;
        float vw = fmaxf(v1, 0.0f) + 1.0f;
        float theta = 3.14f / (1.0f + expf(-v2));   // 3.14 * sigmoid(v2)
        float s, co;
        sincosf(theta, &s, &co);
        float ivh2 = 0.5f / (vh * vh);              // 1/(2 vh^2)
        float ivw2 = 0.5f / (vw * vw);              // 1/(2 vw^2)
        float a  = co * co * ivh2 + s * s * ivw2;
        // reference stores b = s*co/2 * (1/vw^2 - 1/vh^2); we store 2b:
        // 2b = s*co*(1/vw^2 - 1/vh^2) = 2*s*co*(ivw2 - ivh2)
        float b2 = 2.0f * s * co * (ivw2 - ivh2);
        float c  = s * s * ivh2 + co * co * ivw2;
        float pen = (seg[b * NPIX + pix] > 0.7f) ? 0.0f : 3.0e30f;
        g_coef[idx] = make_float4(a, b2, c, pen);

        // block-reduce max(vh, vw)
        float m = fmaxf(vh, vw);
        #pragma unroll
        for (int o = 16; o > 0; o >>= 1)
            m = fmaxf(m, __shfl_xor_sync(0xFFFFFFFFu, m, o));
        __shared__ float wmax[NTHR / 32];
        if ((tid & 31) == 0) wmax[tid >> 5] = m;
        __syncthreads();
        if (tid == 0) {
            float bm = wmax[0];
            #pragma unroll
            for (int w = 1; w < NTHR / 32; w++) bm = fmaxf(bm, wmax[w]);
            atomicMax(&g_varmax, __float_as_int(bm));
        }
    }

    // ---------------- Grid barrier (all 100 blocks co-resident) ----------------
    __syncthreads();
    if (tid == 0) {
        __threadfence();                          // publish g_coef + g_varmax
        atomicAdd(&g_bar, 1u);
        while (atomicAdd(&g_bar, 0u) < gridDim.x) {}
    }
    __syncthreads();
    __threadfence();                              // acquire side (flushes L1D)

    // ---------------- Phase 2: windowed min of quadratic form ----------------
    {
        float vmax = __int_as_float(g_varmax);
        // E >= r^2/(2*vmax^2); need E <= -ln(0.7) ~= 0.356676 -> r <= 0.84460*vmax
        int R = (int)(0.84461f * vmax) + 1;
        if (R > HH - 1) R = HH - 1;

        int i = pix / WW;        // output row (p)
        int j = pix - i * WW;    // output col (q)
        int r0 = max(i - R, 0), r1 = min(i + R, HH - 1);
        int c0 = max(j - R, 0), c1 = min(j + R, WW - 1);
        const float4* cf = g_coef + b * NPIX;

        float minE = 3.0e30f;
        for (int r = r0; r <= r1; r++) {
            float dx = (float)(i - r);
            float dx2 = dx * dx;
            const float4* row = cf + r * WW;
            #pragma unroll 4
            for (int cc = c0; cc <= c1; cc++) {
                float4 k = row[cc];                // plain coherent load (data written this kernel)
                float dy = (float)(j - cc);
                float E = fmaf(k.x, dx2, k.w);     // a*dx^2 + penalty
                E = fmaf(k.y, dx * dy, E);         // + 2b*dx*dy
                E = fmaf(k.z, dy * dy, E);         // + c*dy^2
                minE = fminf(minE, E);
            }
        }
        float pooled = expf(1e-7f - minE);         // exp(-minE + eps)
        out[idx] = (pooled >= 0.7f) ? pooled : 0.0f;
    }

    // ---------------- Self-reset for next graph replay ----------------
    if (tid == 0) {
        unsigned t = atomicAdd(&g_done, 1u);
        if (t == gridDim.x - 1) {                  // last block out restores state
            g_bar = 0;
            g_done = 0;
            g_varmax = 0;
        }
    }
}

extern "C" void kernel_launch(void* const* d_in, const int* in_sizes, int n_in,
                              void* d_out, int out_size) {
    const float* var = (const float*)d_in[0];   // [2,3,80,80]
    const float* seg = (const float*)d_in[1];   // [2,1,80,80]
    float* out = (float*)d_out;                 // [2,1,80,80]
    fused_kernel<<<NBLK, NTHR>>>(var, seg, out);
}

// round 4
// speedup vs baseline: 1.8932x; 1.2292x over previous
#include <cuda_runtime.h>
#include <math.h>

#define BB 2
#define HH 80
#define WW 80
#define NPIX (HH * WW)

#define TW 16            // tile width  (cols, j)
#define TH 8             // tile height (rows, i)
#define NTHR (TW * TH)   // 128 threads
#define RMAX 16          // max radius supported by SMEM staging (slow path beyond)
#define RGH (TH + 2 * RMAX)   // 40 region rows
#define RGW (TW + 2 * RMAX)   // 48 region cols (float4 stride)

__device__ __forceinline__ float4 center_coef(float v0, float v1, float v2, float sg) {
    float vh = fmaxf(v0, 0.0f) + 1.0f;
    float vw = fmaxf(v1, 0.0f) + 1.0f;
    float theta = 3.14f / (1.0f + expf(-v2));      // 3.14 * sigmoid(v2)
    float s, co;
    sincosf(theta, &s, &co);
    float ivh2 = 0.5f / (vh * vh);                 // 1/(2 vh^2)
    float ivw2 = 0.5f / (vw * vw);                 // 1/(2 vw^2)
    float a  = co * co * ivh2 + s * s * ivw2;
    float b2 = 2.0f * s * co * (ivw2 - ivh2);      // 2*b of reference
    float c  = s * s * ivh2 + co * co * ivw2;
    float pen = (sg > 0.7f) ? 0.0f : 3.0e30f;
    return make_float4(a, b2, c, pen);
}

__global__ void __launch_bounds__(NTHR) fused_tile_kernel(const float* __restrict__ var,
                                                          const float* __restrict__ seg,
                                                          float* __restrict__ out) {
    __shared__ float4 s_coef[RGH * RGW];           // 30 KB
    __shared__ float s_red[NTHR / 32];
    __shared__ float s_vmax;

    const int tx = threadIdx.x;                    // 0..15
    const int ty = threadIdx.y;                    // 0..7
    const int tid = ty * TW + tx;
    const int b  = blockIdx.z;
    const int i0 = blockIdx.y * TH;
    const int j0 = blockIdx.x * TW;
    const float* vb = var + b * 3 * NPIX;
    const float* sb = seg + b * NPIX;

    // ---- 1. vmax over this batch's channels 0,1 (contiguous 2*NPIX floats) ----
    float m = 0.0f;
    for (int k = tid; k < 2 * NPIX; k += NTHR)
        m = fmaxf(m, vb[k]);
    #pragma unroll
    for (int o = 16; o > 0; o >>= 1)
        m = fmaxf(m, __shfl_xor_sync(0xFFFFFFFFu, m, o));
    if ((tid & 31) == 0) s_red[tid >> 5] = m;
    __syncthreads();
    if (tid == 0) {
        float bm = s_red[0];
        #pragma unroll
        for (int w = 1; w < NTHR / 32; w++) bm = fmaxf(bm, s_red[w]);
        s_vmax = fmaxf(bm, 0.0f) + 1.0f;
    }
    __syncthreads();

    // E >= r^2/(2*vmax^2); relevant only if E <= -ln(0.7) ~ 0.356676 -> r <= 0.84460*vmax
    int R = (int)(0.84461f * s_vmax) + 1;
    if (R > HH - 1) R = HH - 1;

    const int i = i0 + ty;                         // this thread's output row (p)
    const int j = j0 + tx;                         // this thread's output col (q)
    float minE = 3.0e30f;

    if (R <= RMAX) {
        // ---- 2. fill SMEM with region coefficients (tile + R halo) ----
        const int r0 = max(i0 - R, 0), r1 = min(i0 + TH - 1 + R, HH - 1);
        const int c0 = max(j0 - R, 0), c1 = min(j0 + TW - 1 + R, WW - 1);
        const int rh = r1 - r0 + 1, rw = c1 - c0 + 1;
        for (int k = tid; k < rh * rw; k += NTHR) {
            int rr = k / rw;
            int cc = k - rr * rw;
            int g = (r0 + rr) * WW + (c0 + cc);
            s_coef[rr * RGW + cc] =
                center_coef(vb[g], vb[NPIX + g], vb[2 * NPIX + g], sb[g]);
        }
        __syncthreads();

        // ---- 3. windowed min over SMEM coefficients ----
        const int wr0 = max(i - R, 0), wr1 = min(i + R, HH - 1);
        const int wc0 = max(j - R, 0), wc1 = min(j + R, WW - 1);
        for (int r = wr0; r <= wr1; r++) {
            float dx = (float)(i - r);
            float dx2 = dx * dx;
            const float4* row = s_coef + (r - r0) * RGW - c0;
            #pragma unroll 4
            for (int cc = wc0; cc <= wc1; cc++) {
                float4 k = row[cc];
                float dy = (float)(j - cc);
                float E = fmaf(k.x, dx2, k.w);     // a*dx^2 + penalty
                E = fmaf(k.y, dx * dy, E);         // + 2b*dx*dy
                E = fmaf(k.z, dy * dy, E);         // + c*dy^2
                minE = fminf(minE, E);
            }
        }
    } else {
        // ---- slow path (never triggers for sane inputs): full scan, on-the-fly coef ----
        for (int r = 0; r < HH; r++) {
            float dx = (float)(i - r);
            float dx2 = dx * dx;
            for (int cc = 0; cc < WW; cc++) {
                int g = r * WW + cc;
                float4 k = center_coef(vb[g], vb[NPIX + g], vb[2 * NPIX + g], sb[g]);
                float dy = (float)(j - cc);
                float E = fmaf(k.x, dx2, k.w);
                E = fmaf(k.y, dx * dy, E);
                E = fmaf(k.z, dy * dy, E);
                minE = fminf(minE, E);
            }
        }
    }

    float pooled = expf(1e-7f - minE);             // exp(-minE + eps)
    out[(b * HH + i) * WW + j] = (pooled >= 0.7f) ? pooled : 0.0f;
}

extern "C" void kernel_launch(void* const* d_in, const int* in_sizes, int n_in,
                              void* d_out, int out_size) {
    const float* var = (const float*)d_in[0];   // [2,3,80,80]
    const float* seg = (const float*)d_in[1];   // [2,1,80,80]
    float* out = (float*)d_out;                 // [2,1,80,80]
    fused_tile_kernel<<<dim3(WW / TW, HH / TH, BB), dim3(TW, TH)>>>(var, seg, out);
}